// round 7
// baseline (speedup 1.0000x reference)
#include <cuda_runtime.h>
#include <stdint.h>

// BagEmbedding: out[b,l,:] = sum_{k<50} W[X[b,l,k], :]   (W[0]==0, so the
// reference's X!=0 mask is a value no-op; gathering row 0 is harmless)
// X: (64,128,50) int32, W: (100000,128) fp32, out: (64,128,128) fp32
//
// Persistent wave-balanced grid: exactly 148*3 = 444 blocks (one full
// resident wave at 3 CTAs/SM), each grid-striding over row-groups of 8.
// Double-buffered SMEM index staging so the next group's indices load
// while the current group's gathers are in flight.

#define NB_WORDS 50
#define EMBED    128
#define ROWS     (64 * 128)          // 8192
#define WARPS_PER_BLOCK 8
#define IDX_PER_GROUP (WARPS_PER_BLOCK * NB_WORDS)   // 400
#define NUM_GROUPS (ROWS / WARPS_PER_BLOCK)          // 1024
#define GRID_BLOCKS (148 * 3)                        // 444

__global__ __launch_bounds__(256, 3) void bag_embedding_kernel(
    const int* __restrict__ X,
    const float4* __restrict__ W4,   // W as rows of 32 float4
    float4* __restrict__ out4)
{
    __shared__ int sidx[2][IDX_PER_GROUP];

    const int tid  = threadIdx.x;
    const int warp = tid >> 5;
    const int lane = tid & 31;

    // Prefetch first group's indices into buffer 0.
    int g = blockIdx.x;
    if (g < NUM_GROUPS) {
        const int* __restrict__ xblk = X + (size_t)g * IDX_PER_GROUP;
        #pragma unroll
        for (int i = tid; i < IDX_PER_GROUP; i += 256)
            sidx[0][i] = xblk[i];
    }

    int buf = 0;
    for (; g < NUM_GROUPS; g += GRID_BLOCKS, buf ^= 1) {
        __syncthreads();   // staged indices for group g are visible

        // Prefetch next group's indices into the other buffer (overlaps
        // with this group's gathers; no sync needed until next iter).
        const int gn = g + GRID_BLOCKS;
        if (gn < NUM_GROUPS) {
            const int* __restrict__ xnext = X + (size_t)gn * IDX_PER_GROUP;
            #pragma unroll
            for (int i = tid; i < IDX_PER_GROUP; i += 256)
                sidx[buf ^ 1][i] = xnext[i];
        }

        const int* __restrict__ srow = sidx[buf] + warp * NB_WORDS;

        float4 a0 = make_float4(0.f, 0.f, 0.f, 0.f);
        float4 a1 = make_float4(0.f, 0.f, 0.f, 0.f);
        float4 a2 = make_float4(0.f, 0.f, 0.f, 0.f);
        float4 a3 = make_float4(0.f, 0.f, 0.f, 0.f);

        #pragma unroll
        for (int k = 0; k < NB_WORDS; k += 4) {
            const int i0 = srow[k];
            const int i1 = srow[k + 1];
            const float4 v0 = __ldg(W4 + (size_t)i0 * (EMBED / 4) + lane);
            const float4 v1 = __ldg(W4 + (size_t)i1 * (EMBED / 4) + lane);

            float4 v2 = make_float4(0.f, 0.f, 0.f, 0.f);
            float4 v3 = make_float4(0.f, 0.f, 0.f, 0.f);
            if (k + 2 < NB_WORDS) {
                const int i2 = srow[k + 2];
                v2 = __ldg(W4 + (size_t)i2 * (EMBED / 4) + lane);
            }
            if (k + 3 < NB_WORDS) {
                const int i3 = srow[k + 3];
                v3 = __ldg(W4 + (size_t)i3 * (EMBED / 4) + lane);
            }

            a0.x += v0.x; a0.y += v0.y; a0.z += v0.z; a0.w += v0.w;
            a1.x += v1.x; a1.y += v1.y; a1.z += v1.z; a1.w += v1.w;
            a2.x += v2.x; a2.y += v2.y; a2.z += v2.z; a2.w += v2.w;
            a3.x += v3.x; a3.y += v3.y; a3.z += v3.z; a3.w += v3.w;
        }

        float4 acc;
        acc.x = (a0.x + a1.x) + (a2.x + a3.x);
        acc.y = (a0.y + a1.y) + (a2.y + a3.y);
        acc.z = (a0.z + a1.z) + (a2.z + a3.z);
        acc.w = (a0.w + a1.w) + (a2.w + a3.w);

        const int row = g * WARPS_PER_BLOCK + warp;
        out4[(size_t)row * (EMBED / 4) + lane] = acc;
    }
}

extern "C" void kernel_launch(void* const* d_in, const int* in_sizes, int n_in,
                              void* d_out, int out_size)
{
    const int*    X = (const int*)d_in[0];
    const float4* W = (const float4*)d_in[1];
    float4*     out = (float4*)d_out;

    bag_embedding_kernel<<<GRID_BLOCKS, 256>>>(X, W, out);
}